// round 10
// baseline (speedup 1.0000x reference)
#include <cuda_runtime.h>
#include <cuda_bf16.h>

#define NQ    18
#define NBAT  16

// Sum/difference-basis MPS sweep.
// Forward (d-sector, coords sd,dd,p), per site:   [5 FMAs]
//   t1 = sd + 2sin(t0)*p ; t3 = 0.5sin(t0)*sd + p
//   sd' = cos(t1)*cos(t0)*dd ; dd' = cos(t1)*t1 ; p' = -sin(t1)*t3
// Backward (u-sector), per site: uu' = cos(t0)*uu + 2(1-cos(t0))  [1 FMA]
//   (u00+u11 == 4 conserved; u01_i = 2 sin(t0_{i+1}), u01_17 = 2)
// Readout: Z_i = sd_i + dd_i*(0.5*uu_i - 1) + p_i * u01_i
// (verified vs brute force on 1- and 2-qubit corner cases incl. u01 term)

__shared__ float4 g_cA[NQ][NBAT];   // {2 s0, 0.5 s0, c1*c0, c1}
__shared__ float  g_cE[NQ][NBAT];   // -s1
__shared__ float2 g_cU[NQ][NBAT];   // {c0, 2(1-c0)}
__shared__ float4 g_L [NQ][NBAT];   // (sd, dd, p, pad) per site
__shared__ float  g_U [NQ][NBAT];   // uu per site

__global__ void __launch_bounds__(128, 1)
quantum_mps_kernel(const float* __restrict__ in, float* __restrict__ out) {
    const int tid = threadIdx.x;

    // ---- phase 1: constants. 288 (site,batch) pairs over 128 threads.
    #pragma unroll
    for (int j = 0; j < 3; j++) {
        const int q = tid + 128 * j;
        if (q < 288) {
            const int b = q / 18, s = q % 18;
            float s0, c0, s1, c1;
            __sincosf(in[b * 36 + s],      &s0, &c0);   // full angle, layer 0
            __sincosf(in[b * 36 + 18 + s], &s1, &c1);   // full angle, layer 1
            g_cA[s][b] = make_float4(s0 + s0, 0.5f * s0, c1 * c0, c1);
            g_cE[s][b] = -s1;
            g_cU[s][b] = make_float2(c0, 2.0f - (c0 + c0));
        }
    }
    __syncthreads();

    // ---- phase 2: fused forward+backward sweep, one convergent warp (16 lanes)
    if (tid < NBAT) {
        const int b = tid;
        float sd = 1.0f, dd = 1.0f, p = 0.0f;   // d-sector of L
        float uu = 2.0f;                         // u00 of S
        g_U[NQ - 1][b] = 2.0f;
        #pragma unroll
        for (int t = 0; t < NQ; t++) {
            const float4 a = g_cA[t][b];
            const float  e = g_cE[t][b];
            // forward site t
            const float t1 = fmaf(a.x, p, sd);
            const float t3 = fmaf(a.y, sd, p);
            sd = a.z * dd;
            dd = a.w * t1;
            p  = e   * t3;
            g_L[t][b] = make_float4(sd, dd, p, 0.0f);
            // backward site 17-t  (produces uu_{16-t})
            if (t < NQ - 1) {
                const float2 u = g_cU[NQ - 1 - t][b];
                uu = fmaf(u.x, uu, u.y);
                g_U[NQ - 2 - t][b] = uu;
            }
        }
    }
    __syncthreads();

    // ---- phase 3: readout, 288 outputs over 128 threads
    #pragma unroll
    for (int j = 0; j < 3; j++) {
        const int q = tid + 128 * j;
        if (q < 288) {
            const int b = q / 18, s = q % 18;
            const float4 L  = g_L[s][b];
            const float  uu = g_U[s][b];
            const float q01 = (s < NQ - 1) ? g_cA[s + 1][b].x : 2.0f;
            const float z = fmaf(L.z, q01,
                            fmaf(L.y, fmaf(0.5f, uu, -1.0f), L.x));
            out[b * NQ + s] = z;
        }
    }
}

extern "C" void kernel_launch(void* const* d_in, const int* in_sizes, int n_in,
                              void* d_out, int out_size) {
    const float* in  = (const float*)d_in[0];
    float*       out = (float*)d_out;
    quantum_mps_kernel<<<1, 128>>>(in, out);
}

// round 11
// speedup vs baseline: 1.4145x; 1.4145x over previous
#include <cuda_runtime.h>
#include <cuda_bf16.h>

#define NQ    18
#define NBAT  16
#define NTHR  (NQ * NBAT)   // 288: one thread per (batch, site)

// Sum/difference-basis MPS, forward sweep only.
// Derivation chain (verified R2..R9, each step bench-passed):
//   - 8-state bond -> 6-state symmetric subspace -> u/d decoupling.
//   - Backward u-sector: uu == 2 identically (uu' = c0*uu + 2 - 2c0, uu_17 = 2),
//     so the dd readout term fma(0.5,uu,-1) == 0 exactly -> no backward sweep.
// Per site i (coords sd, dd, p):
//   t1 = 2*s0*p + sd ; t3 = 0.5*s0*sd + p
//   sd' = (c1*c0)*dd ; dd' = c1*t1 ; p' = -s1*t3
//   Z_i = sd' + q01*p',  q01 = 2*s0_{i+1} (2.0 for i = 17)

__shared__ float4 g_cA[NQ][NBAT];   // {2*s0, 0.5*s0, c1*c0, c1}
__shared__ float  g_cE[NQ][NBAT];   // -s1

__global__ void __launch_bounds__(NTHR, 1)
quantum_mps_kernel(const float* __restrict__ in, float* __restrict__ out) {
    const int tid = threadIdx.x;

    // ---- phase 1: one (batch, site) per thread: 2 loads, 2 sincosf, pack
    {
        const int b = tid / NQ, s = tid % NQ;
        float s0, c0, s1, c1;
        __sincosf(in[b * 36 + s],      &s0, &c0);   // layer 0, full angle
        __sincosf(in[b * 36 + 18 + s], &s1, &c1);   // layer 1, full angle
        g_cA[s][b] = make_float4(s0 + s0, 0.5f * s0, c1 * c0, c1);
        g_cE[s][b] = -s1;
    }
    __syncthreads();

    // ---- phase 2: forward sweep + in-loop readout, one warp (16 lanes)
    if (tid < NBAT) {
        const int b = tid;
        float sd = 1.0f, dd = 1.0f, p = 0.0f;
        #pragma unroll
        for (int t = 0; t < NQ; t++) {
            const float4 a = g_cA[t][b];
            const float  e = g_cE[t][b];
            const float t1 = fmaf(a.x, p, sd);
            const float t3 = fmaf(a.y, sd, p);
            sd = a.z * dd;
            dd = a.w * t1;
            p  = e   * t3;
            const float q01 = (t < NQ - 1) ? g_cA[t + 1][b].x : 2.0f;
            out[b * NQ + t] = fmaf(q01, p, sd);
        }
    }
}

extern "C" void kernel_launch(void* const* d_in, const int* in_sizes, int n_in,
                              void* d_out, int out_size) {
    const float* in  = (const float*)d_in[0];
    float*       out = (float*)d_out;
    quantum_mps_kernel<<<1, NTHR>>>(in, out);
}